// round 2
// baseline (speedup 1.0000x reference)
#include <cuda_runtime.h>
#include <math.h>

#define Lq   4096
#define NFFT 8192
#define Hh   512
#define Bb   8
#define Nn   64

// ---------------- scratch (device globals: no runtime allocation) ----------------
__device__ float  g_K[Hh * Lq];          // time-domain kernel K[h,l]
__device__ float2 g_Kd[Hh * NFFT];       // spectrum of K (full complex, 8192 bins)
__device__ float2 g_tw[NFFT / 2];        // twiddles exp(-2*pi*i*j/8192), j<4096
__device__ float4 g_coef[Hh * Nn];       // (qr, qi, coeff_re, coeff_im)

// ---------------- twiddle table ----------------
__global__ void tw_kernel() {
    int j = blockIdx.x * blockDim.x + threadIdx.x;
    if (j < NFFT / 2) {
        double a = -2.0 * M_PI * (double)j / (double)NFFT;
        double s, c;
        sincos(a, &s, &c);
        g_tw[j] = make_float2((float)c, (float)s);
    }
}

// ---------------- per-(h,n) coefficient: closed-form complex-softmax normalizer ----
// Reference: P[l] = q*l, shift = q*lstar (lstar = argmax Re(P)), e = exp(P - shift),
// s = sum_l e[l], S = e * conj(s)/(|s|^2 + 1e-7), K = Re(sum_n (W/Lam)*S).
// Closed form: if Re(q)<=0 (lstar=0): s = (exp(qL)-1)/(exp(q)-1)
//              if Re(q)>0 (lstar=L-1): s = (exp(-qL)-1)/(exp(-q)-1)
// computed in double with expm1 for the denominator (cancellation-safe).
__global__ void coeff_kernel(const float* __restrict__ W,
                             const float* __restrict__ log_step,
                             const float* __restrict__ Lre,
                             const float* __restrict__ Lim) {
    int h = blockIdx.x;
    int n = threadIdx.x;
    float step = expf(log_step[h]);
    float Lr = Lre[n], Li = Lim[n];
    float qr = step * Lr, qi = step * Li;

    double sgn = (qr > 0.f) ? -1.0 : 1.0;
    double pr = sgn * (double)qr, pi = sgn * (double)qi;

    // num = exp(p*L) - 1   (Re(p) <= 0 so exp is bounded; underflow -> -1, correct)
    double eL = exp(pr * (double)Lq);
    double sL, cL;
    sincos(pi * (double)Lq, &sL, &cL);
    double num_re = eL * cL - 1.0;
    double num_im = eL * sL;

    // den = exp(p) - 1, cancellation-safe:
    // Re = expm1(pr)*cos(pi) - 2*sin^2(pi/2),  Im = exp(pr)*sin(pi)
    double sp, cp;
    sincos(pi, &sp, &cp);
    double em1 = expm1(pr);
    double hs  = sin(0.5 * pi);
    double den_re = em1 * cp - 2.0 * hs * hs;
    double den_im = (em1 + 1.0) * sp;
    double dmag = den_re * den_re + den_im * den_im;

    double s_re, s_im;
    if (dmag > 0.0) {
        s_re = (num_re * den_re + num_im * den_im) / dmag;
        s_im = (num_im * den_re - num_re * den_im) / dmag;
    } else {             // q == 0: e[l] == 1 for all l
        s_re = (double)Lq;
        s_im = 0.0;
    }

    // coeff = (Wc/Lam) * conj(s)/(|s|^2 + EPS)
    double w0 = W[(h * Nn + n) * 2 + 0];
    double w1 = W[(h * Nn + n) * 2 + 1];
    double lmag = (double)Lr * Lr + (double)Li * Li;
    double a_re = (w0 * Lr + w1 * Li) / lmag;
    double a_im = (w1 * Lr - w0 * Li) / lmag;
    double smag = s_re * s_re + s_im * s_im + 1e-7;
    double b_re =  s_re / smag;
    double b_im = -s_im / smag;
    float cr = (float)(a_re * b_re - a_im * b_im);
    float ci = (float)(a_re * b_im + a_im * b_re);
    g_coef[h * Nn + n] = make_float4(qr, qi, cr, ci);
}

// ---------------- K[h,l] = Re sum_n coeff_n * exp(q_n * (l - lstar_n)) -------------
// 256 threads = 64 l-chunks (64 wide) x 4 n-groups (16 n each). Exact exp/sincos
// anchor per (thread,n), then complex-multiply recurrence IN THE DECAYING DIRECTION
// so underflow-to-zero is always the correct limit.
__global__ void k_kernel() {
    extern __shared__ float kbuf[];     // 4 * 4096 floats
    int h   = blockIdx.x;
    int tid = threadIdx.x;
    int c   = tid & 63;                 // l-chunk index
    int g   = tid >> 6;                 // n-group
    int l0  = c << 6;

    float acc[64];
#pragma unroll
    for (int j = 0; j < 64; j++) acc[j] = 0.f;

    for (int nn = 0; nn < 16; nn++) {
        int n = (g << 4) + nn;
        float4 cf = g_coef[h * Nn + n];
        float qr = cf.x, qi = cf.y, cr = cf.z, ci = cf.w;

        if (qr <= 0.f) {
            // lstar = 0, decaying forward
            float d0 = (float)l0;
            float mr = expf(qr * d0);           // underflow->0 is correct
            float sph, cph;
            sincosf(qi * d0, &sph, &cph);
            float ar = mr * cph, ai = mr * sph;
            float em = expf(qr);
            float sl, cl2;
            sincosf(qi, &sl, &cl2);
            float lr = em * cl2, li = em * sl;  // lambda, |lambda| <= 1
#pragma unroll
            for (int j = 0; j < 64; j++) {
                acc[j] += cr * ar - ci * ai;
                float t2 = ar * lr - ai * li;
                ai = ar * li + ai * lr;
                ar = t2;
            }
        } else {
            // lstar = L-1, anchor at chunk END, iterate backward with lambda^-1
            float d0 = (float)(l0 + 63 - (Lq - 1));   // <= 0
            float mr = expf(qr * d0);
            float sph, cph;
            sincosf(qi * d0, &sph, &cph);
            float ar = mr * cph, ai = mr * sph;
            float em = expf(-qr);
            float sl, cl2;
            sincosf(-qi, &sl, &cl2);
            float lr = em * cl2, li = em * sl;  // lambda^-1, |.| < 1
#pragma unroll
            for (int j = 63; j >= 0; j--) {
                acc[j] += cr * ar - ci * ai;
                float t2 = ar * lr - ai * li;
                ai = ar * li + ai * lr;
                ar = t2;
            }
        }
    }

#pragma unroll
    for (int j = 0; j < 64; j++) kbuf[g * Lq + l0 + j] = acc[j];
    __syncthreads();
    for (int i = tid; i < Lq; i += 256) {
        g_K[h * Lq + i] = kbuf[i] + kbuf[Lq + i] + kbuf[2 * Lq + i] + kbuf[3 * Lq + i];
    }
}

// ---------------- 8192-pt radix-2 Stockham FFT in shared memory --------------------
// Natural order in -> natural order out, ping-pong buffers. 512 threads.
// Key identity: input pair is always (X[j], X[j+4096]); twiddle index = j with the
// low `stage` bits cleared; outputs at j+pp and j+pp+2^stage.
__device__ __forceinline__ float2 cmulf(float2 a, float2 b) {
    return make_float2(a.x * b.x - a.y * b.y, a.x * b.y + a.y * b.x);
}

__device__ float2* fft8192(float2* A, float2* B, int tid) {
    float2* X = A;
    float2* Y = B;
    for (int stage = 0; stage < 13; stage++) {
        int mask = (1 << stage) - 1;
#pragma unroll
        for (int r = 0; r < 8; r++) {
            int j  = tid + (r << 9);
            int pp = j & ~mask;               // p << stage
            float2 a = X[j];
            float2 b = X[j + 4096];
            float2 w = g_tw[pp];
            float2 u = make_float2(a.x + b.x, a.y + b.y);
            float2 v = make_float2(a.x - b.x, a.y - b.y);
            int o = j + pp;
            Y[o] = u;
            Y[o + (mask + 1)] = cmulf(v, w);
        }
        __syncthreads();
        float2* t = X; X = Y; Y = t;
    }
    return X;   // 13 swaps -> result lives in the B buffer
}

// ---------------- FFT of K rows ----------------
__global__ void fftK_kernel() {
    extern __shared__ float2 sm[];
    float2* A  = sm;
    float2* Bf = sm + NFFT;
    int h = blockIdx.x;
    int tid = threadIdx.x;
#pragma unroll
    for (int r = 0; r < 8; r++) {
        int l = tid + (r << 9);
        A[l]        = make_float2(g_K[h * Lq + l], 0.f);
        A[l + 4096] = make_float2(0.f, 0.f);
    }
    __syncthreads();
    float2* R = fft8192(A, Bf, tid);
#pragma unroll
    for (int r = 0; r < 16; r++) {
        int k = tid + (r << 9);
        g_Kd[h * NFFT + k] = R[k];
    }
}

// ---------------- conv: per-(b,h) row: FFT, * Kd, IFFT (conj trick), + D*u ---------
__global__ void conv_kernel(const float* __restrict__ u,
                            const float* __restrict__ D,
                            float* __restrict__ out) {
    extern __shared__ float2 sm[];
    float2* A  = sm;
    float2* Bf = sm + NFFT;
    int row = blockIdx.x;            // b*H + h
    int h   = row & (Hh - 1);
    int tid = threadIdx.x;
    const float* urow = u + (size_t)row * Lq;

    float ur[8];
#pragma unroll
    for (int r = 0; r < 8; r++) {
        int l = tid + (r << 9);
        float v = urow[l];
        ur[r] = v;
        A[l]        = make_float2(v, 0.f);
        A[l + 4096] = make_float2(0.f, 0.f);
    }
    __syncthreads();

    float2* R = fft8192(A, Bf, tid);

    // pointwise multiply by Kd[h], then conjugate (ifft(Z) = conj(fft(conj Z))/N)
    const float2* Kd = g_Kd + (size_t)h * NFFT;
#pragma unroll
    for (int r = 0; r < 16; r++) {
        int k = tid + (r << 9);
        float2 z = cmulf(R[k], Kd[k]);
        R[k] = make_float2(z.x, -z.y);
    }
    __syncthreads();

    float2* other = (R == A) ? Bf : A;
    float2* R2 = fft8192(R, other, tid);

    float dh = D[h];
    float* orow = out + (size_t)row * Lq;
    const float inv = 1.0f / (float)NFFT;
#pragma unroll
    for (int r = 0; r < 8; r++) {
        int l = tid + (r << 9);
        orow[l] = R2[l].x * inv + dh * ur[r];
    }
}

// ---------------- launcher ----------------
extern "C" void kernel_launch(void* const* d_in, const int* in_sizes, int n_in,
                              void* d_out, int out_size) {
    const float* u  = (const float*)d_in[0];
    const float* W  = (const float*)d_in[1];
    const float* D  = (const float*)d_in[2];
    const float* ls = (const float*)d_in[3];
    const float* Lr = (const float*)d_in[4];
    const float* Li = (const float*)d_in[5];
    float* out = (float*)d_out;

    // opt-in smem (idempotent, not a stream op -> graph-capture safe)
    cudaFuncSetAttribute(k_kernel,    cudaFuncAttributeMaxDynamicSharedMemorySize,
                         4 * Lq * (int)sizeof(float));
    cudaFuncSetAttribute(fftK_kernel, cudaFuncAttributeMaxDynamicSharedMemorySize,
                         2 * NFFT * (int)sizeof(float2));
    cudaFuncSetAttribute(conv_kernel, cudaFuncAttributeMaxDynamicSharedMemorySize,
                         2 * NFFT * (int)sizeof(float2));

    tw_kernel<<<(NFFT / 2 + 255) / 256, 256>>>();
    coeff_kernel<<<Hh, Nn>>>(W, ls, Lr, Li);
    k_kernel<<<Hh, 256, 4 * Lq * sizeof(float)>>>();
    fftK_kernel<<<Hh, 512, 2 * NFFT * sizeof(float2)>>>();
    conv_kernel<<<Bb * Hh, 512, 2 * NFFT * sizeof(float2)>>>(u, D, out);
}

// round 3
// speedup vs baseline: 2.7383x; 2.7383x over previous
#include <cuda_runtime.h>
#include <math.h>

#define Lq   4096
#define NFFT 8192
#define Mh   4096           // half-size (packed) FFT length
#define Hh   512
#define Bb   8
#define Nn   64
#define GSTRIDE 4104        // rfft bins 0..4096 per h, padded

// ---------------- scratch (device globals) ----------------
__device__ float  g_K[Hh * Lq];          // time-domain kernel K[h,l]
__device__ float2 g_G[Hh * GSTRIDE];     // rfft8192(K): bins 0..4096
__device__ float2 g_tw[NFFT / 2];        // exp(-2*pi*i*j/8192), j<4096
__device__ float4 g_coef[Hh * Nn];       // (qr, qi, coeff_re, coeff_im)

// smem padding to kill bank conflicts on low-stride stages
#define PD(i) ((i) + ((i) >> 4))
#define SMEMN 4352                        // PD(4095)=4350 < 4352

__device__ __forceinline__ float2 cmulf(float2 a, float2 b) {
    return make_float2(fmaf(a.x, b.x, -a.y * b.y), fmaf(a.x, b.y, a.y * b.x));
}

// ---------------- twiddle table ----------------
__global__ void tw_kernel() {
    int j = blockIdx.x * blockDim.x + threadIdx.x;
    if (j < NFFT / 2) {
        double a = -2.0 * M_PI * (double)j / (double)NFFT;
        double s, c;
        sincos(a, &s, &c);
        g_tw[j] = make_float2((float)c, (float)s);
    }
}

// ---------------- per-(h,n) coefficient (closed-form complex-softmax sum) --------
__global__ void coeff_kernel(const float* __restrict__ W,
                             const float* __restrict__ log_step,
                             const float* __restrict__ Lre,
                             const float* __restrict__ Lim) {
    int h = blockIdx.x;
    int n = threadIdx.x;
    float step = expf(log_step[h]);
    float Lr = Lre[n], Li = Lim[n];
    float qr = step * Lr, qi = step * Li;

    double sgn = (qr > 0.f) ? -1.0 : 1.0;
    double pr = sgn * (double)qr, pi = sgn * (double)qi;

    double eL = exp(pr * (double)Lq);
    double sL, cL;
    sincos(pi * (double)Lq, &sL, &cL);
    double num_re = eL * cL - 1.0;
    double num_im = eL * sL;

    double sp, cp;
    sincos(pi, &sp, &cp);
    double em1 = expm1(pr);
    double hs  = sin(0.5 * pi);
    double den_re = em1 * cp - 2.0 * hs * hs;
    double den_im = (em1 + 1.0) * sp;
    double dmag = den_re * den_re + den_im * den_im;

    double s_re, s_im;
    if (dmag > 0.0) {
        s_re = (num_re * den_re + num_im * den_im) / dmag;
        s_im = (num_im * den_re - num_re * den_im) / dmag;
    } else {
        s_re = (double)Lq;
        s_im = 0.0;
    }

    double w0 = W[(h * Nn + n) * 2 + 0];
    double w1 = W[(h * Nn + n) * 2 + 1];
    double lmag = (double)Lr * Lr + (double)Li * Li;
    double a_re = (w0 * Lr + w1 * Li) / lmag;
    double a_im = (w1 * Lr - w0 * Li) / lmag;
    double smag = s_re * s_re + s_im * s_im + 1e-7;
    double b_re =  s_re / smag;
    double b_im = -s_im / smag;
    float cr = (float)(a_re * b_re - a_im * b_im);
    float ci = (float)(a_re * b_im + a_im * b_re);
    g_coef[h * Nn + n] = make_float4(qr, qi, cr, ci);
}

// ---------------- K[h,l] = Re sum_n coeff_n * exp(q_n * (l - lstar_n)) -----------
__global__ void k_kernel() {
    extern __shared__ float kbuf[];     // 4 * 4096 floats
    int h   = blockIdx.x;
    int tid = threadIdx.x;
    int c   = tid & 63;
    int g   = tid >> 6;
    int l0  = c << 6;

    float acc[64];
#pragma unroll
    for (int j = 0; j < 64; j++) acc[j] = 0.f;

    for (int nn = 0; nn < 16; nn++) {
        int n = (g << 4) + nn;
        float4 cf = g_coef[h * Nn + n];
        float qr = cf.x, qi = cf.y, cr = cf.z, ci = cf.w;

        if (qr <= 0.f) {
            float d0 = (float)l0;
            float mr = expf(qr * d0);
            float sph, cph;
            sincosf(qi * d0, &sph, &cph);
            float ar = mr * cph, ai = mr * sph;
            float em = expf(qr);
            float sl, cl2;
            sincosf(qi, &sl, &cl2);
            float lr = em * cl2, li = em * sl;
#pragma unroll
            for (int j = 0; j < 64; j++) {
                acc[j] += cr * ar - ci * ai;
                float t2 = ar * lr - ai * li;
                ai = ar * li + ai * lr;
                ar = t2;
            }
        } else {
            float d0 = (float)(l0 + 63 - (Lq - 1));
            float mr = expf(qr * d0);
            float sph, cph;
            sincosf(qi * d0, &sph, &cph);
            float ar = mr * cph, ai = mr * sph;
            float em = expf(-qr);
            float sl, cl2;
            sincosf(-qi, &sl, &cl2);
            float lr = em * cl2, li = em * sl;
#pragma unroll
            for (int j = 63; j >= 0; j--) {
                acc[j] += cr * ar - ci * ai;
                float t2 = ar * lr - ai * li;
                ai = ar * li + ai * lr;
                ar = t2;
            }
        }
    }

#pragma unroll
    for (int j = 0; j < 64; j++) kbuf[g * Lq + l0 + j] = acc[j];
    __syncthreads();
    for (int i = tid; i < Lq; i += 256) {
        g_K[h * Lq + i] = kbuf[i] + kbuf[Lq + i] + kbuf[2 * Lq + i] + kbuf[3 * Lq + i];
    }
}

// ---------------- 4096-pt radix-4 (fused 2x radix-2) Stockham FFT -----------------
// 256 threads, 4 butterflies/thread, padded ping-pong smem. Natural in/out.
// Derivation: two consecutive radix-2 Stockham stages fused; per fused stage s
// (L=4^s), butterfly t: inputs X[t + r*1024]; pp = t & ~(L-1), q = t - pp;
// w1 = e^{-2pi*i*pp/4096}, second pair twiddle = w1*(-i), next-stage tw = w1^2;
// outputs at 4*pp + q + {0, L, 2L, 3L}.
__device__ float2* fft4096(float2* X, float2* Y, int tid) {
#pragma unroll
    for (int s = 0; s < 6; s++) {
        int L = 1 << (2 * s);
#pragma unroll
        for (int b = 0; b < 4; b++) {
            int t  = tid + (b << 8);
            int q  = t & (L - 1);
            int pp = t - q;
            float2 w1 = g_tw[pp << 1];
            float2 a  = X[PD(t)];
            float2 bb = X[PD(t + 2048)];
            float2 c  = X[PD(t + 1024)];
            float2 d  = X[PD(t + 3072)];
            float2 u0  = make_float2(a.x + bb.x, a.y + bb.y);
            float2 v0r = make_float2(a.x - bb.x, a.y - bb.y);
            float2 u1  = make_float2(c.x + d.x, c.y + d.y);
            float2 v1r = make_float2(c.x - d.x, c.y - d.y);
            float2 v0 = cmulf(v0r, w1);
            float2 w1mi = make_float2(w1.y, -w1.x);         // w1 * (-i)
            float2 v1 = cmulf(v1r, w1mi);
            float2 w2 = cmulf(w1, w1);
            int base = 3 * pp + t;                          // 4*pp + q
            Y[PD(base)]         = make_float2(u0.x + u1.x, u0.y + u1.y);
            Y[PD(base + L)]     = make_float2(v0.x + v1.x, v0.y + v1.y);
            Y[PD(base + 2 * L)] = cmulf(make_float2(u0.x - u1.x, u0.y - u1.y), w2);
            Y[PD(base + 3 * L)] = cmulf(make_float2(v0.x - v1.x, v0.y - v1.y), w2);
        }
        __syncthreads();
        float2* tmp = X; X = Y; Y = tmp;
    }
    return X;   // 6 swaps -> result back in the input buffer
}

// ---------------- rfft8192 of K rows via packed fft4096 + split -------------------
__global__ __launch_bounds__(256) void fftG_kernel() {
    extern __shared__ float2 sm[];
    float2* A  = sm;
    float2* B2 = sm + SMEMN;
    int h = blockIdx.x, tid = threadIdx.x;
    const float2* k2 = (const float2*)(g_K + (size_t)h * Lq);
#pragma unroll
    for (int r = 0; r < 8; r++) {
        int m = tid + (r << 8);
        A[PD(m)]        = k2[m];
        A[PD(m + 2048)] = make_float2(0.f, 0.f);
    }
    __syncthreads();
    float2* R = fft4096(A, B2, tid);
    float2* G = g_G + (size_t)h * GSTRIDE;
#pragma unroll
    for (int r = 0; r < 8; r++) {
        int k = tid + (r << 8);
        if (k == 0) {
            float2 z0 = R[PD(0)];
            G[0]    = make_float2(z0.x + z0.y, 0.f);
            G[4096] = make_float2(z0.x - z0.y, 0.f);
            float2 z2 = R[PD(2048)];
            G[2048] = make_float2(z2.x, -z2.y);
        } else {
            float2 zk = R[PD(k)], zm = R[PD(4096 - k)];
            float2 xe = make_float2(0.5f * (zk.x + zm.x), 0.5f * (zk.y - zm.y));
            float2 xo = make_float2(0.5f * (zk.y + zm.y), -0.5f * (zk.x - zm.x));
            float2 w = g_tw[k];
            float2 wxo = cmulf(w, xo);
            G[k]        = make_float2(xe.x + wxo.x, xe.y + wxo.y);
            G[4096 - k] = make_float2(xe.x - wxo.x, -(xe.y - wxo.y));
        }
    }
}

// ---------------- conv: rfft-packed forward, *G, packed inverse, + D*u ------------
__global__ __launch_bounds__(256, 3) void conv_kernel(const float* __restrict__ u,
                                                      const float* __restrict__ D,
                                                      float* __restrict__ out) {
    extern __shared__ float2 sm[];
    float2* A  = sm;
    float2* B2 = sm + SMEMN;
    int row = blockIdx.x;            // b*H + h
    int h   = row & (Hh - 1);
    int tid = threadIdx.x;
    const float2* u2 = (const float2*)(u + (size_t)row * Lq);

    float2 ur[8];
#pragma unroll
    for (int r = 0; r < 8; r++) {
        int m = tid + (r << 8);
        float2 v = u2[m];
        ur[r] = v;
        A[PD(m)]        = v;                       // z[m] = u[2m] + i*u[2m+1]
        A[PD(m + 2048)] = make_float2(0.f, 0.f);   // zero-pad
    }
    __syncthreads();

    float2* R1 = fft4096(A, B2, tid);
    float2* S  = (R1 == A) ? B2 : A;

    // split -> X[k]; multiply by G; merge -> Zy; store conj(Zy) (ifft conj trick)
    const float2* G = g_G + (size_t)h * GSTRIDE;
#pragma unroll
    for (int r = 0; r < 8; r++) {
        int k = tid + (r << 8);
        if (k == 0) {
            float2 z0 = R1[PD(0)];
            float x0 = z0.x + z0.y;
            float xM = z0.x - z0.y;
            float y0 = x0 * G[0].x;
            float yM = xM * G[4096].x;
            S[PD(0)] = make_float2(0.5f * (y0 + yM), -0.5f * (y0 - yM));
            float2 z2 = R1[PD(2048)];
            S[PD(2048)] = cmulf(make_float2(z2.x, -z2.y), G[2048]);
        } else {
            float2 zk = R1[PD(k)];
            float2 zm = R1[PD(4096 - k)];
            float2 xe = make_float2(0.5f * (zk.x + zm.x), 0.5f * (zk.y - zm.y));
            float2 xo = make_float2(0.5f * (zk.y + zm.y), -0.5f * (zk.x - zm.x));
            float2 w  = g_tw[k];
            float2 wxo = cmulf(w, xo);
            float2 xf = make_float2(xe.x + wxo.x, xe.y + wxo.y);          // X[k]
            float2 xb = make_float2(xe.x - wxo.x, -(xe.y - wxo.y));       // X[M-k]
            float2 ya = cmulf(xf, G[k]);
            float2 yb = cmulf(xb, G[4096 - k]);
            float2 ye = make_float2(0.5f * (ya.x + yb.x), 0.5f * (ya.y - yb.y));
            float2 dd = make_float2(ya.x - yb.x, ya.y + yb.y);
            float2 wc = make_float2(w.x, -w.y);
            float2 yo = cmulf(wc, dd);
            yo.x *= 0.5f; yo.y *= 0.5f;
            // Zy[k] = (ye.x - yo.y, ye.y + yo.x); Zy[M-k] = (ye.x + yo.y, -ye.y + yo.x)
            S[PD(k)]        = make_float2(ye.x - yo.y, -(ye.y + yo.x));   // conj stored
            S[PD(4096 - k)] = make_float2(ye.x + yo.y, ye.y - yo.x);      // conj stored
        }
    }
    __syncthreads();

    float2* R2 = fft4096(S, R1, tid);

    float dh = D[h];
    float2* o2 = (float2*)(out + (size_t)row * Lq);
    const float inv = 1.0f / (float)Mh;
#pragma unroll
    for (int r = 0; r < 8; r++) {
        int m = tid + (r << 8);
        float2 z = R2[PD(m)];
        float2 uu = ur[r];
        // z' = conj(R2)/M : y[2m]=Re, y[2m+1]=Im
        o2[m] = make_float2(fmaf(dh, uu.x, z.x * inv),
                            fmaf(dh, uu.y, -z.y * inv));
    }
}

// ---------------- launcher ----------------
extern "C" void kernel_launch(void* const* d_in, const int* in_sizes, int n_in,
                              void* d_out, int out_size) {
    const float* u  = (const float*)d_in[0];
    const float* W  = (const float*)d_in[1];
    const float* D  = (const float*)d_in[2];
    const float* ls = (const float*)d_in[3];
    const float* Lr = (const float*)d_in[4];
    const float* Li = (const float*)d_in[5];
    float* out = (float*)d_out;

    int fft_smem = 2 * SMEMN * (int)sizeof(float2);   // 69632 B

    cudaFuncSetAttribute(k_kernel,    cudaFuncAttributeMaxDynamicSharedMemorySize,
                         4 * Lq * (int)sizeof(float));
    cudaFuncSetAttribute(fftG_kernel, cudaFuncAttributeMaxDynamicSharedMemorySize,
                         fft_smem);
    cudaFuncSetAttribute(conv_kernel, cudaFuncAttributeMaxDynamicSharedMemorySize,
                         fft_smem);

    tw_kernel<<<(NFFT / 2 + 255) / 256, 256>>>();
    coeff_kernel<<<Hh, Nn>>>(W, ls, Lr, Li);
    k_kernel<<<Hh, 256, 4 * Lq * sizeof(float)>>>();
    fftG_kernel<<<Hh, 256, fft_smem>>>();
    conv_kernel<<<Bb * Hh, 256, fft_smem>>>(u, D, out);
}

// round 4
// speedup vs baseline: 3.5871x; 1.3100x over previous
#include <cuda_runtime.h>
#include <math.h>

#define Lq   4096
#define NFFT 8192
#define Mh   4096
#define Hh   512
#define Bb   8
#define Nn   64
#define GSTRIDE 4104

// ---------------- scratch (device globals) ----------------
__device__ float  g_K[Hh * Lq];
__device__ float2 g_G[Hh * GSTRIDE];
__device__ float2 g_tw[NFFT / 2];        // W_8192^j, j<4096
__device__ float4 g_coef[Hh * Nn];

#define PD(i) ((i) + ((i) >> 4))
#define PDN 4352                          // PD(4095)=4350

__device__ __forceinline__ float2 cmulf(float2 a, float2 b) {
    return make_float2(fmaf(a.x, b.x, -a.y * b.y), fmaf(a.x, b.y, a.y * b.x));
}
__device__ __forceinline__ float2 cadd(float2 a, float2 b){return make_float2(a.x+b.x,a.y+b.y);}
__device__ __forceinline__ float2 csub(float2 a, float2 b){return make_float2(a.x-b.x,a.y-b.y);}

// DFT-4: q_m = sum_a p_a * W4^{a*m}
#define DFT4(p0,p1,p2,p3,q0,q1,q2,q3) { \
    float2 t0=cadd(p0,p2), t1=csub(p0,p2), t2=cadd(p1,p3), t3=csub(p1,p3); \
    q0=cadd(t0,t2); q2=csub(t0,t2); \
    q1=make_float2(t1.x+t3.y, t1.y-t3.x); \
    q3=make_float2(t1.x-t3.y, t1.y+t3.x); }

// ---- f32x2 packed helpers ----
__device__ __forceinline__ unsigned long long pk2(float lo, float hi){
    unsigned long long r; asm("mov.b64 %0,{%1,%2};":"=l"(r):"f"(lo),"f"(hi)); return r;
}
__device__ __forceinline__ void upk2(unsigned long long v, float& lo, float& hi){
    asm("mov.b64 {%0,%1},%2;":"=f"(lo),"=f"(hi):"l"(v));
}
__device__ __forceinline__ unsigned long long f2fma(unsigned long long a, unsigned long long b, unsigned long long c){
    unsigned long long r; asm("fma.rn.f32x2 %0,%1,%2,%3;":"=l"(r):"l"(a),"l"(b),"l"(c)); return r;
}
__device__ __forceinline__ unsigned long long f2mul(unsigned long long a, unsigned long long b){
    unsigned long long r; asm("mul.rn.f32x2 %0,%1,%2;":"=l"(r):"l"(a),"l"(b)); return r;
}

// ---------------- twiddle table ----------------
__global__ void tw_kernel() {
    int j = blockIdx.x * blockDim.x + threadIdx.x;
    if (j < NFFT / 2) {
        double a = -2.0 * M_PI * (double)j / (double)NFFT;
        double s, c;
        sincos(a, &s, &c);
        g_tw[j] = make_float2((float)c, (float)s);
    }
}

// ---------------- coeff kernel (unchanged, verified) ----------------
__global__ void coeff_kernel(const float* __restrict__ W,
                             const float* __restrict__ log_step,
                             const float* __restrict__ Lre,
                             const float* __restrict__ Lim) {
    int h = blockIdx.x;
    int n = threadIdx.x;
    float step = expf(log_step[h]);
    float Lr = Lre[n], Li = Lim[n];
    float qr = step * Lr, qi = step * Li;

    double sgn = (qr > 0.f) ? -1.0 : 1.0;
    double pr = sgn * (double)qr, pi = sgn * (double)qi;

    double eL = exp(pr * (double)Lq);
    double sL, cL;
    sincos(pi * (double)Lq, &sL, &cL);
    double num_re = eL * cL - 1.0;
    double num_im = eL * sL;

    double sp, cp;
    sincos(pi, &sp, &cp);
    double em1 = expm1(pr);
    double hs  = sin(0.5 * pi);
    double den_re = em1 * cp - 2.0 * hs * hs;
    double den_im = (em1 + 1.0) * sp;
    double dmag = den_re * den_re + den_im * den_im;

    double s_re, s_im;
    if (dmag > 0.0) {
        s_re = (num_re * den_re + num_im * den_im) / dmag;
        s_im = (num_im * den_re - num_re * den_im) / dmag;
    } else {
        s_re = (double)Lq;
        s_im = 0.0;
    }

    double w0 = W[(h * Nn + n) * 2 + 0];
    double w1 = W[(h * Nn + n) * 2 + 1];
    double lmag = (double)Lr * Lr + (double)Li * Li;
    double a_re = (w0 * Lr + w1 * Li) / lmag;
    double a_im = (w1 * Lr - w0 * Li) / lmag;
    double smag = s_re * s_re + s_im * s_im + 1e-7;
    double b_re =  s_re / smag;
    double b_im = -s_im / smag;
    float cr = (float)(a_re * b_re - a_im * b_im);
    float ci = (float)(a_re * b_im + a_im * b_re);
    g_coef[h * Nn + n] = make_float4(qr, qi, cr, ci);
}

// ---------------- K via f32x2 packed recurrence (same n, two l-chunks) -----------
__global__ __launch_bounds__(256) void k_kernel() {
    extern __shared__ float kbuf[];     // 4 * 4096 floats
    int h   = blockIdx.x;
    int tid = threadIdx.x;
    int cp  = tid & 63;                 // chunk-pair index
    int g   = tid >> 6;                 // n-group (16 n each)
    int l0a = cp * 32;
    int l0b = l0a + 2048;

    unsigned long long acc[32];
#pragma unroll
    for (int j = 0; j < 32; j++) acc[j] = 0ULL;

    for (int nn = 0; nn < 16; nn++) {
        int n = (g << 4) + nn;
        float4 cf = g_coef[h * Nn + n];
        float qr = cf.x, qi = cf.y, cr = cf.z, ci = cf.w;
        bool fwd = (qr <= 0.f);

        float ara, aia, arb, aib, lrS, liS;
        if (fwd) {
            float d0a = (float)l0a, d0b = (float)l0b;
            float ma = expf(qr * d0a), mb = expf(qr * d0b);
            float sa, ca2, sb, cb2;
            sincosf(qi * d0a, &sa, &ca2);
            sincosf(qi * d0b, &sb, &cb2);
            ara = ma * ca2; aia = ma * sa;
            arb = mb * cb2; aib = mb * sb;
            float em = expf(qr);
            float sl, cl2; sincosf(qi, &sl, &cl2);
            lrS = em * cl2; liS = em * sl;
        } else {
            float d0a = (float)(l0a + 31 - (Lq - 1));
            float d0b = (float)(l0b + 31 - (Lq - 1));
            float ma = expf(qr * d0a), mb = expf(qr * d0b);
            float sa, ca2, sb, cb2;
            sincosf(qi * d0a, &sa, &ca2);
            sincosf(qi * d0b, &sb, &cb2);
            ara = ma * ca2; aia = ma * sa;
            arb = mb * cb2; aib = mb * sb;
            float em = expf(-qr);
            float sl, cl2; sincosf(-qi, &sl, &cl2);
            lrS = em * cl2; liS = em * sl;
        }

        unsigned long long ar2 = pk2(ara, arb), ai2 = pk2(aia, aib);
        unsigned long long lr2 = pk2(lrS, lrS), li2 = pk2(liS, liS);
        unsigned long long nli2 = pk2(-liS, -liS);
        unsigned long long cr2 = pk2(cr, cr),  nci2 = pk2(-ci, -ci);

        if (fwd) {
#pragma unroll
            for (int j = 0; j < 32; j++) {
                acc[j] = f2fma(cr2, ar2, f2fma(nci2, ai2, acc[j]));
                unsigned long long t = f2fma(ar2, lr2, f2mul(ai2, nli2));
                ai2 = f2fma(ar2, li2, f2mul(ai2, lr2));
                ar2 = t;
            }
        } else {
#pragma unroll
            for (int j = 31; j >= 0; j--) {
                acc[j] = f2fma(cr2, ar2, f2fma(nci2, ai2, acc[j]));
                unsigned long long t = f2fma(ar2, lr2, f2mul(ai2, nli2));
                ai2 = f2fma(ar2, li2, f2mul(ai2, lr2));
                ar2 = t;
            }
        }
    }

#pragma unroll
    for (int j = 0; j < 32; j++) {
        float a, b; upk2(acc[j], a, b);
        kbuf[g * Lq + l0a + j] = a;
        kbuf[g * Lq + l0b + j] = b;
    }
    __syncthreads();
    for (int i = tid; i < Lq; i += 256) {
        g_K[h * Lq + i] = kbuf[i] + kbuf[Lq + i] + kbuf[2 * Lq + i] + kbuf[3 * Lq + i];
    }
}

// ---------------- 4096-pt radix-16 Stockham FFT, in-place, single smem buffer ----
// Stage s: L = 16^s. Thread t: q = t&(L-1), pp = t-q. Reads X[t+256r], computes
// y_m = (DFT16 of x)_m * W4096^{pp*m}, writes X[16pp + q + m*L].
// DFT16 split: r = b+4a; A_b[m1] = DFT4_a(x_{b+4a}); y_{m1+4m2} =
//   DFT4_b( A_b[m1] * W16^{b*m1} * W4096^{pp*m1} ) * W4096^{4*pp*m2}.
__device__ void fft4096(float2* X, int tid) {
#pragma unroll
    for (int s = 0; s < 3; s++) {
        const int L = (s == 0) ? 1 : (s == 1) ? 16 : 256;
        int q  = tid & (L - 1);
        int pp = tid - q;
        float2 x[16];
#pragma unroll
        for (int r = 0; r < 16; r++) x[r] = X[PD(tid + (r << 8))];
        __syncthreads();

        float2 w1  = g_tw[pp << 1];          // W_4096^pp
        float2 w2  = cmulf(w1, w1);
        float2 w3  = cmulf(w2, w1);
        float2 w4  = cmulf(w2, w2);
        float2 w8  = cmulf(w4, w4);
        float2 w12 = cmulf(w8, w4);

        float2 A0[4], A1[4], A2[4], A3[4];
        DFT4(x[0], x[4], x[8],  x[12], A0[0], A0[1], A0[2], A0[3]);
        DFT4(x[1], x[5], x[9],  x[13], A1[0], A1[1], A1[2], A1[3]);
        DFT4(x[2], x[6], x[10], x[14], A2[0], A2[1], A2[2], A2[3]);
        DFT4(x[3], x[7], x[11], x[15], A3[0], A3[1], A3[2], A3[3]);

        const float c8 = 0.9238795325112867f, s8 = 0.3826834323650898f,
                    r2 = 0.7071067811865476f;
        const float2 W16_1 = make_float2( c8, -s8);
        const float2 W16_2 = make_float2( r2, -r2);
        const float2 W16_3 = make_float2( s8, -c8);
        const float2 W16_6 = make_float2(-r2, -r2);
        const float2 W16_9 = make_float2(-c8,  s8);

        float2 y[16];
        // m1 = 0
        DFT4(A0[0], A1[0], A2[0], A3[0], y[0], y[4], y[8], y[12]);
        // m1 = 1: twiddles W16^{b}, folded with w1
        {
            float2 v0 = cmulf(A0[1], w1);
            float2 v1 = cmulf(A1[1], cmulf(W16_1, w1));
            float2 v2 = cmulf(A2[1], cmulf(W16_2, w1));
            float2 v3 = cmulf(A3[1], cmulf(W16_3, w1));
            DFT4(v0, v1, v2, v3, y[1], y[5], y[9], y[13]);
        }
        // m1 = 2: twiddles W16^{2b} = {1, W16_2, -i, W16_6}, folded with w2
        {
            float2 v0 = cmulf(A0[2], w2);
            float2 v1 = cmulf(A1[2], cmulf(W16_2, w2));
            float2 v2 = cmulf(A2[2], make_float2(w2.y, -w2.x));   // -i * w2
            float2 v3 = cmulf(A3[2], cmulf(W16_6, w2));
            DFT4(v0, v1, v2, v3, y[2], y[6], y[10], y[14]);
        }
        // m1 = 3: twiddles W16^{3b} = {1, W16_3, W16_6, W16_9}, folded with w3
        {
            float2 v0 = cmulf(A0[3], w3);
            float2 v1 = cmulf(A1[3], cmulf(W16_3, w3));
            float2 v2 = cmulf(A2[3], cmulf(W16_6, w3));
            float2 v3 = cmulf(A3[3], cmulf(W16_9, w3));
            DFT4(v0, v1, v2, v3, y[3], y[7], y[11], y[15]);
        }
#pragma unroll
        for (int m1 = 0; m1 < 4; m1++) {
            y[m1 + 4]  = cmulf(y[m1 + 4],  w4);
            y[m1 + 8]  = cmulf(y[m1 + 8],  w8);
            y[m1 + 12] = cmulf(y[m1 + 12], w12);
        }
        int ob = (pp << 4) + q;
#pragma unroll
        for (int m = 0; m < 16; m++) X[PD(ob + m * L)] = y[m];
        __syncthreads();
    }
}

// ---------------- rfft8192(K) -> G -------------------------------------------------
__global__ __launch_bounds__(256) void fftG_kernel() {
    extern __shared__ float2 sm[];
    int h = blockIdx.x, tid = threadIdx.x;
    const float2* k2 = (const float2*)(g_K + (size_t)h * Lq);
#pragma unroll
    for (int r = 0; r < 8; r++) {
        int m = tid + (r << 8);
        sm[PD(m)]        = k2[m];
        sm[PD(m + 2048)] = make_float2(0.f, 0.f);
    }
    __syncthreads();
    fft4096(sm, tid);
    float2* G = g_G + (size_t)h * GSTRIDE;
#pragma unroll
    for (int r = 0; r < 8; r++) {
        int k = tid + (r << 8);
        if (k == 0) {
            float2 z0 = sm[PD(0)];
            G[0]    = make_float2(z0.x + z0.y, 0.f);
            G[4096] = make_float2(z0.x - z0.y, 0.f);
            float2 z2 = sm[PD(2048)];
            G[2048] = make_float2(z2.x, -z2.y);
        } else {
            float2 zk = sm[PD(k)], zm = sm[PD(4096 - k)];
            float2 xe = make_float2(0.5f * (zk.x + zm.x), 0.5f * (zk.y - zm.y));
            float2 xo = make_float2(0.5f * (zk.y + zm.y), -0.5f * (zk.x - zm.x));
            float2 w = g_tw[k];
            float2 wxo = cmulf(w, xo);
            G[k]        = make_float2(xe.x + wxo.x, xe.y + wxo.y);
            G[4096 - k] = make_float2(xe.x - wxo.x, -(xe.y - wxo.y));
        }
    }
}

// ---------------- conv: packed rfft fwd, *G, packed inverse, + D*u -----------------
__global__ __launch_bounds__(256) void conv_kernel(const float* __restrict__ u,
                                                   const float* __restrict__ D,
                                                   float* __restrict__ out) {
    extern __shared__ float2 sm[];
    int row = blockIdx.x;
    int h   = row & (Hh - 1);
    int tid = threadIdx.x;
    const float2* u2 = (const float2*)(u + (size_t)row * Lq);

    float2 ur[8];
#pragma unroll
    for (int r = 0; r < 8; r++) {
        int m = tid + (r << 8);
        float2 v = u2[m];
        ur[r] = v;
        sm[PD(m)]        = v;
        sm[PD(m + 2048)] = make_float2(0.f, 0.f);
    }
    __syncthreads();

    fft4096(sm, tid);

    // middle: split -> *G -> merge -> store conj, in-place (read all, sync, write)
    const float2* G = g_G + (size_t)h * GSTRIDE;
    float2 sa[8], sb[8], z2048;
#pragma unroll
    for (int r = 0; r < 8; r++) {
        int k = tid + (r << 8);
        sa[r] = sm[PD(k)];
        sb[r] = (k == 0) ? make_float2(0.f, 0.f) : sm[PD(4096 - k)];
    }
    if (tid == 0) z2048 = sm[PD(2048)];
    __syncthreads();
#pragma unroll
    for (int r = 0; r < 8; r++) {
        int k = tid + (r << 8);
        if (k == 0) {
            float2 z0 = sa[0];
            float x0 = z0.x + z0.y;
            float xM = z0.x - z0.y;
            float y0 = x0 * G[0].x;
            float yM = xM * G[4096].x;
            sm[PD(0)] = make_float2(0.5f * (y0 + yM), -0.5f * (y0 - yM));
            sm[PD(2048)] = cmulf(make_float2(z2048.x, -z2048.y), G[2048]);
        } else {
            float2 zk = sa[r];
            float2 zm = sb[r];
            float2 xe = make_float2(0.5f * (zk.x + zm.x), 0.5f * (zk.y - zm.y));
            float2 xo = make_float2(0.5f * (zk.y + zm.y), -0.5f * (zk.x - zm.x));
            float2 w  = g_tw[k];
            float2 wxo = cmulf(w, xo);
            float2 xf = make_float2(xe.x + wxo.x, xe.y + wxo.y);
            float2 xb = make_float2(xe.x - wxo.x, -(xe.y - wxo.y));
            float2 ya = cmulf(xf, G[k]);
            float2 yb = cmulf(xb, G[4096 - k]);
            float2 ye = make_float2(0.5f * (ya.x + yb.x), 0.5f * (ya.y - yb.y));
            float2 dd = make_float2(ya.x - yb.x, ya.y + yb.y);
            float2 wc = make_float2(w.x, -w.y);
            float2 yo = cmulf(wc, dd);
            yo.x *= 0.5f; yo.y *= 0.5f;
            sm[PD(k)]        = make_float2(ye.x - yo.y, -(ye.y + yo.x));
            sm[PD(4096 - k)] = make_float2(ye.x + yo.y, ye.y - yo.x);
        }
    }
    __syncthreads();

    fft4096(sm, tid);

    float dh = D[h];
    float2* o2 = (float2*)(out + (size_t)row * Lq);
    const float inv = 1.0f / (float)Mh;
#pragma unroll
    for (int r = 0; r < 8; r++) {
        int m = tid + (r << 8);
        float2 z = sm[PD(m)];
        float2 uu = ur[r];
        o2[m] = make_float2(fmaf(dh, uu.x, z.x * inv),
                            fmaf(dh, uu.y, -z.y * inv));
    }
}

// ---------------- launcher ----------------
extern "C" void kernel_launch(void* const* d_in, const int* in_sizes, int n_in,
                              void* d_out, int out_size) {
    const float* u  = (const float*)d_in[0];
    const float* W  = (const float*)d_in[1];
    const float* D  = (const float*)d_in[2];
    const float* ls = (const float*)d_in[3];
    const float* Lr = (const float*)d_in[4];
    const float* Li = (const float*)d_in[5];
    float* out = (float*)d_out;

    int fft_smem = PDN * (int)sizeof(float2);         // 34816 B
    int k_smem   = 4 * Lq * (int)sizeof(float);       // 65536 B

    cudaFuncSetAttribute(k_kernel,    cudaFuncAttributeMaxDynamicSharedMemorySize, k_smem);
    cudaFuncSetAttribute(fftG_kernel, cudaFuncAttributeMaxDynamicSharedMemorySize, fft_smem);
    cudaFuncSetAttribute(conv_kernel, cudaFuncAttributeMaxDynamicSharedMemorySize, fft_smem);

    tw_kernel<<<(NFFT / 2 + 255) / 256, 256>>>();
    coeff_kernel<<<Hh, Nn>>>(W, ls, Lr, Li);
    k_kernel<<<Hh, 256, k_smem>>>();
    fftG_kernel<<<Hh, 256, fft_smem>>>();
    conv_kernel<<<Bb * Hh, 256, fft_smem>>>(u, D, out);
}

// round 5
// speedup vs baseline: 3.9014x; 1.0876x over previous
#include <cuda_runtime.h>
#include <math.h>

#define Lq   4096
#define NFFT 8192
#define Mh   4096
#define Hh   512
#define Bb   8
#define Nn   64
#define GSTRIDE 4104

__device__ float  g_K[Hh * Lq];
__device__ float2 g_G[Hh * GSTRIDE];
__device__ float2 g_tw[NFFT / 2];        // W_8192^j, j<4096
__device__ float4 g_coef[Hh * Nn];

#define PD(i) ((i) + ((i) >> 4))
#define PDN 4352

__device__ __forceinline__ float2 cmulf(float2 a, float2 b) {
    return make_float2(fmaf(a.x, b.x, -a.y * b.y), fmaf(a.x, b.y, a.y * b.x));
}
__device__ __forceinline__ float2 cadd(float2 a, float2 b){return make_float2(a.x+b.x,a.y+b.y);}
__device__ __forceinline__ float2 csub(float2 a, float2 b){return make_float2(a.x-b.x,a.y-b.y);}

#define DFT4(p0,p1,p2,p3,q0,q1,q2,q3) { \
    float2 t0=cadd(p0,p2), t1=csub(p0,p2), t2=cadd(p1,p3), t3=csub(p1,p3); \
    q0=cadd(t0,t2); q2=csub(t0,t2); \
    q1=make_float2(t1.x+t3.y, t1.y-t3.x); \
    q3=make_float2(t1.x-t3.y, t1.y+t3.x); }

// DFT4 with p2=p3=0 (zero-padded half)
#define DFT4H(p0,p1,q0,q1,q2,q3) { \
    q0=cadd(p0,p1); q2=csub(p0,p1); \
    q1=make_float2(p0.x+p1.y, p0.y-p1.x); \
    q3=make_float2(p0.x-p1.y, p0.y+p1.x); }

// DFT4 outputs 0,1 only
#define DFT4_01(p0,p1,p2,p3,q0,q1) { \
    float2 t0=cadd(p0,p2), t1=csub(p0,p2), t2=cadd(p1,p3), t3=csub(p1,p3); \
    q0=cadd(t0,t2); q1=make_float2(t1.x+t3.y, t1.y-t3.x); }

#define W16_1 make_float2( 0.9238795325112867f, -0.3826834323650898f)
#define W16_2 make_float2( 0.7071067811865476f, -0.7071067811865476f)
#define W16_3 make_float2( 0.3826834323650898f, -0.9238795325112867f)
#define W16_6 make_float2(-0.7071067811865476f, -0.7071067811865476f)
#define W16_9 make_float2(-0.9238795325112867f,  0.3826834323650898f)

#define ALAYER(x,A0,A1,A2,A3) { \
    DFT4(x[0],x[4],x[8],x[12], A0[0],A0[1],A0[2],A0[3]); \
    DFT4(x[1],x[5],x[9],x[13], A1[0],A1[1],A1[2],A1[3]); \
    DFT4(x[2],x[6],x[10],x[14],A2[0],A2[1],A2[2],A2[3]); \
    DFT4(x[3],x[7],x[11],x[15],A3[0],A3[1],A3[2],A3[3]); }

#define ALAYER_HALF(z,A0,A1,A2,A3) { \
    DFT4H(z[0],z[4],A0[0],A0[1],A0[2],A0[3]); \
    DFT4H(z[1],z[5],A1[0],A1[1],A1[2],A1[3]); \
    DFT4H(z[2],z[6],A2[0],A2[1],A2[2],A2[3]); \
    DFT4H(z[3],z[7],A3[0],A3[1],A3[2],A3[3]); }

// full DFT16 B-layer with outer twiddles W4096^{pp*m} folded; w1 = W4096^pp
#define BLAYER_TW(A0,A1,A2,A3,y,W1IN) { \
    float2 w1=(W1IN); \
    float2 w2=cmulf(w1,w1), w3=cmulf(w2,w1), w4=cmulf(w2,w2); \
    float2 w8=cmulf(w4,w4), w12=cmulf(w8,w4); \
    DFT4(A0[0],A1[0],A2[0],A3[0], y[0],y[4],y[8],y[12]); \
    { float2 v0=cmulf(A0[1],w1); \
      float2 v1=cmulf(A1[1],cmulf(W16_1,w1)); \
      float2 v2=cmulf(A2[1],cmulf(W16_2,w1)); \
      float2 v3=cmulf(A3[1],cmulf(W16_3,w1)); \
      DFT4(v0,v1,v2,v3, y[1],y[5],y[9],y[13]); } \
    { float2 v0=cmulf(A0[2],w2); \
      float2 v1=cmulf(A1[2],cmulf(W16_2,w2)); \
      float2 v2=cmulf(A2[2],make_float2(w2.y,-w2.x)); \
      float2 v3=cmulf(A3[2],cmulf(W16_6,w2)); \
      DFT4(v0,v1,v2,v3, y[2],y[6],y[10],y[14]); } \
    { float2 v0=cmulf(A0[3],w3); \
      float2 v1=cmulf(A1[3],cmulf(W16_3,w3)); \
      float2 v2=cmulf(A2[3],cmulf(W16_6,w3)); \
      float2 v3=cmulf(A3[3],cmulf(W16_9,w3)); \
      DFT4(v0,v1,v2,v3, y[3],y[7],y[11],y[15]); } \
    _Pragma("unroll") \
    for (int m1=0;m1<4;m1++){ \
        y[m1+4]=cmulf(y[m1+4],w4); y[m1+8]=cmulf(y[m1+8],w8); y[m1+12]=cmulf(y[m1+12],w12); } }

// DFT16 B-layer, unit outer twiddles (pp==0)
#define BLAYER_UNIT(A0,A1,A2,A3,y) { \
    DFT4(A0[0],A1[0],A2[0],A3[0], y[0],y[4],y[8],y[12]); \
    { float2 v1=cmulf(A1[1],W16_1), v2=cmulf(A2[1],W16_2), v3=cmulf(A3[1],W16_3); \
      DFT4(A0[1],v1,v2,v3, y[1],y[5],y[9],y[13]); } \
    { float2 v1=cmulf(A1[2],W16_2); \
      float2 v2=make_float2(A2[2].y,-A2[2].x); \
      float2 v3=cmulf(A3[2],W16_6); \
      DFT4(A0[2],v1,v2,v3, y[2],y[6],y[10],y[14]); } \
    { float2 v1=cmulf(A1[3],W16_3), v2=cmulf(A2[3],W16_6), v3=cmulf(A3[3],W16_9); \
      DFT4(A0[3],v1,v2,v3, y[3],y[7],y[11],y[15]); } }

// unit B-layer, outputs y[0..7] only (bins < 2048)
#define BLAYER_UNIT_HALF(A0,A1,A2,A3,y) { \
    DFT4_01(A0[0],A1[0],A2[0],A3[0], y[0],y[4]); \
    { float2 v1=cmulf(A1[1],W16_1), v2=cmulf(A2[1],W16_2), v3=cmulf(A3[1],W16_3); \
      DFT4_01(A0[1],v1,v2,v3, y[1],y[5]); } \
    { float2 v1=cmulf(A1[2],W16_2); \
      float2 v2=make_float2(A2[2].y,-A2[2].x); \
      float2 v3=cmulf(A3[2],W16_6); \
      DFT4_01(A0[2],v1,v2,v3, y[2],y[6]); } \
    { float2 v1=cmulf(A1[3],W16_3), v2=cmulf(A2[3],W16_6), v3=cmulf(A3[3],W16_9); \
      DFT4_01(A0[3],v1,v2,v3, y[3],y[7]); } }

// ---- f32x2 packed helpers ----
__device__ __forceinline__ unsigned long long pk2(float lo, float hi){
    unsigned long long r; asm("mov.b64 %0,{%1,%2};":"=l"(r):"f"(lo),"f"(hi)); return r;
}
__device__ __forceinline__ void upk2(unsigned long long v, float& lo, float& hi){
    asm("mov.b64 {%0,%1},%2;":"=f"(lo),"=f"(hi):"l"(v));
}
__device__ __forceinline__ unsigned long long f2fma(unsigned long long a, unsigned long long b, unsigned long long c){
    unsigned long long r; asm("fma.rn.f32x2 %0,%1,%2,%3;":"=l"(r):"l"(a),"l"(b),"l"(c)); return r;
}
__device__ __forceinline__ unsigned long long f2mul(unsigned long long a, unsigned long long b){
    unsigned long long r; asm("mul.rn.f32x2 %0,%1,%2;":"=l"(r):"l"(a),"l"(b)); return r;
}

// ---------------- twiddle table ----------------
__global__ void tw_kernel() {
    int j = blockIdx.x * blockDim.x + threadIdx.x;
    if (j < NFFT / 2) {
        double a = -2.0 * M_PI * (double)j / (double)NFFT;
        double s, c;
        sincos(a, &s, &c);
        g_tw[j] = make_float2((float)c, (float)s);
    }
}

// ---------------- coeff kernel (verified) ----------------
__global__ void coeff_kernel(const float* __restrict__ W,
                             const float* __restrict__ log_step,
                             const float* __restrict__ Lre,
                             const float* __restrict__ Lim) {
    int h = blockIdx.x;
    int n = threadIdx.x;
    float step = expf(log_step[h]);
    float Lr = Lre[n], Li = Lim[n];
    float qr = step * Lr, qi = step * Li;

    double sgn = (qr > 0.f) ? -1.0 : 1.0;
    double pr = sgn * (double)qr, pi = sgn * (double)qi;

    double eL = exp(pr * (double)Lq);
    double sL, cL;
    sincos(pi * (double)Lq, &sL, &cL);
    double num_re = eL * cL - 1.0;
    double num_im = eL * sL;

    double sp, cp;
    sincos(pi, &sp, &cp);
    double em1 = expm1(pr);
    double hs  = sin(0.5 * pi);
    double den_re = em1 * cp - 2.0 * hs * hs;
    double den_im = (em1 + 1.0) * sp;
    double dmag = den_re * den_re + den_im * den_im;

    double s_re, s_im;
    if (dmag > 0.0) {
        s_re = (num_re * den_re + num_im * den_im) / dmag;
        s_im = (num_im * den_re - num_re * den_im) / dmag;
    } else {
        s_re = (double)Lq;
        s_im = 0.0;
    }

    double w0 = W[(h * Nn + n) * 2 + 0];
    double w1 = W[(h * Nn + n) * 2 + 1];
    double lmag = (double)Lr * Lr + (double)Li * Li;
    double a_re = (w0 * Lr + w1 * Li) / lmag;
    double a_im = (w1 * Lr - w0 * Li) / lmag;
    double smag = s_re * s_re + s_im * s_im + 1e-7;
    double b_re =  s_re / smag;
    double b_im = -s_im / smag;
    float cr = (float)(a_re * b_re - a_im * b_im);
    float ci = (float)(a_re * b_im + a_im * b_re);
    g_coef[h * Nn + n] = make_float4(qr, qi, cr, ci);
}

// ---------------- K via f32x2 packed recurrence (verified) ----------------
__global__ __launch_bounds__(256) void k_kernel() {
    extern __shared__ float kbuf[];
    int h   = blockIdx.x;
    int tid = threadIdx.x;
    int cp  = tid & 63;
    int g   = tid >> 6;
    int l0a = cp * 32;
    int l0b = l0a + 2048;

    unsigned long long acc[32];
#pragma unroll
    for (int j = 0; j < 32; j++) acc[j] = 0ULL;

    for (int nn = 0; nn < 16; nn++) {
        int n = (g << 4) + nn;
        float4 cf = g_coef[h * Nn + n];
        float qr = cf.x, qi = cf.y, cr = cf.z, ci = cf.w;
        bool fwd = (qr <= 0.f);

        float ara, aia, arb, aib, lrS, liS;
        if (fwd) {
            float d0a = (float)l0a, d0b = (float)l0b;
            float ma = expf(qr * d0a), mb = expf(qr * d0b);
            float sa, ca2, sb, cb2;
            sincosf(qi * d0a, &sa, &ca2);
            sincosf(qi * d0b, &sb, &cb2);
            ara = ma * ca2; aia = ma * sa;
            arb = mb * cb2; aib = mb * sb;
            float em = expf(qr);
            float sl, cl2; sincosf(qi, &sl, &cl2);
            lrS = em * cl2; liS = em * sl;
        } else {
            float d0a = (float)(l0a + 31 - (Lq - 1));
            float d0b = (float)(l0b + 31 - (Lq - 1));
            float ma = expf(qr * d0a), mb = expf(qr * d0b);
            float sa, ca2, sb, cb2;
            sincosf(qi * d0a, &sa, &ca2);
            sincosf(qi * d0b, &sb, &cb2);
            ara = ma * ca2; aia = ma * sa;
            arb = mb * cb2; aib = mb * sb;
            float em = expf(-qr);
            float sl, cl2; sincosf(-qi, &sl, &cl2);
            lrS = em * cl2; liS = em * sl;
        }

        unsigned long long ar2 = pk2(ara, arb), ai2 = pk2(aia, aib);
        unsigned long long lr2 = pk2(lrS, lrS), li2 = pk2(liS, liS);
        unsigned long long nli2 = pk2(-liS, -liS);
        unsigned long long cr2 = pk2(cr, cr),  nci2 = pk2(-ci, -ci);

        if (fwd) {
#pragma unroll
            for (int j = 0; j < 32; j++) {
                acc[j] = f2fma(cr2, ar2, f2fma(nci2, ai2, acc[j]));
                unsigned long long t = f2fma(ar2, lr2, f2mul(ai2, nli2));
                ai2 = f2fma(ar2, li2, f2mul(ai2, lr2));
                ar2 = t;
            }
        } else {
#pragma unroll
            for (int j = 31; j >= 0; j--) {
                acc[j] = f2fma(cr2, ar2, f2fma(nci2, ai2, acc[j]));
                unsigned long long t = f2fma(ar2, lr2, f2mul(ai2, nli2));
                ai2 = f2fma(ar2, li2, f2mul(ai2, lr2));
                ar2 = t;
            }
        }
    }

#pragma unroll
    for (int j = 0; j < 32; j++) {
        float a, b; upk2(acc[j], a, b);
        kbuf[g * Lq + l0a + j] = a;
        kbuf[g * Lq + l0b + j] = b;
    }
    __syncthreads();
    for (int i = tid; i < Lq; i += 256) {
        g_K[h * Lq + i] = kbuf[i] + kbuf[Lq + i] + kbuf[2 * Lq + i] + kbuf[3 * Lq + i];
    }
}

// ---------------- shared FFT stage 1 (L=16), smem->smem ----------------
__device__ __forceinline__ void fft_stage1(float2* X, int tid) {
    int q = tid & 15, pp = tid - q;
    float2 x[16];
#pragma unroll
    for (int r = 0; r < 16; r++) x[r] = X[PD(tid + (r << 8))];
    __syncthreads();
    float2 A0[4], A1[4], A2[4], A3[4];
    ALAYER(x, A0, A1, A2, A3);
    float2 y[16];
    BLAYER_TW(A0, A1, A2, A3, y, g_tw[pp << 1]);
    int ob = (pp << 4) + q;
#pragma unroll
    for (int m = 0; m < 16; m++) X[PD(ob + (m << 4))] = y[m];
    __syncthreads();
}

// stage 2 (L=256, pp=0 -> unit outer twiddles), smem->smem
__device__ __forceinline__ void fft_stage2_smem(float2* X, int tid) {
    float2 x[16];
#pragma unroll
    for (int r = 0; r < 16; r++) x[r] = X[PD(tid + (r << 8))];
    __syncthreads();
    float2 A0[4], A1[4], A2[4], A3[4];
    ALAYER(x, A0, A1, A2, A3);
    float2 y[16];
    BLAYER_UNIT(A0, A1, A2, A3, y);
#pragma unroll
    for (int m = 0; m < 16; m++) X[PD(tid + (m << 8))] = y[m];
    __syncthreads();
}

// stage 0 (L=1, pp=tid) from registers z[8] (upper half zero), regs->smem
__device__ __forceinline__ void fft_stage0_regs(float2* X, int tid, const float2 z[8]) {
    float2 A0[4], A1[4], A2[4], A3[4];
    ALAYER_HALF(z, A0, A1, A2, A3);
    float2 y[16];
    BLAYER_TW(A0, A1, A2, A3, y, g_tw[tid << 1]);
    int ob = tid << 4;
#pragma unroll
    for (int m = 0; m < 16; m++) X[PD(ob + m)] = y[m];
    __syncthreads();
}

// stage 0 (L=1, pp=tid), full inputs, smem->smem (inverse FFT first stage)
__device__ __forceinline__ void fft_stage0_smem(float2* X, int tid) {
    float2 x[16];
#pragma unroll
    for (int r = 0; r < 16; r++) x[r] = X[PD(tid + (r << 8))];
    __syncthreads();
    float2 A0[4], A1[4], A2[4], A3[4];
    ALAYER(x, A0, A1, A2, A3);
    float2 y[16];
    BLAYER_TW(A0, A1, A2, A3, y, g_tw[tid << 1]);
    int ob = tid << 4;
#pragma unroll
    for (int m = 0; m < 16; m++) X[PD(ob + m)] = y[m];
    __syncthreads();
}

// ---------------- rfft8192(K) -> G ----------------
__global__ __launch_bounds__(256) void fftG_kernel() {
    extern __shared__ float2 sm[];
    int h = blockIdx.x, tid = threadIdx.x;
    const float2* k2 = (const float2*)(g_K + (size_t)h * Lq);
    float2 z[8];
#pragma unroll
    for (int r = 0; r < 8; r++) z[r] = k2[tid + (r << 8)];

    fft_stage0_regs(sm, tid, z);
    fft_stage1(sm, tid);
    fft_stage2_smem(sm, tid);

    float2* G = g_G + (size_t)h * GSTRIDE;
#pragma unroll
    for (int r = 0; r < 8; r++) {
        int k = tid + (r << 8);
        if (k == 0) {
            float2 z0 = sm[PD(0)];
            G[0]    = make_float2(z0.x + z0.y, 0.f);
            G[4096] = make_float2(z0.x - z0.y, 0.f);
            float2 z2 = sm[PD(2048)];
            G[2048] = make_float2(z2.x, -z2.y);
        } else {
            float2 zk = sm[PD(k)], zm = sm[PD(4096 - k)];
            float2 xe = make_float2(0.5f * (zk.x + zm.x), 0.5f * (zk.y - zm.y));
            float2 xo = make_float2(0.5f * (zk.y + zm.y), -0.5f * (zk.x - zm.x));
            float2 w = g_tw[k];
            float2 wxo = cmulf(w, xo);
            G[k]        = make_float2(xe.x + wxo.x, xe.y + wxo.y);
            G[4096 - k] = make_float2(xe.x - wxo.x, -(xe.y - wxo.y));
        }
    }
}

// ---------------- conv ----------------
__global__ __launch_bounds__(256) void conv_kernel(const float* __restrict__ u,
                                                   const float* __restrict__ D,
                                                   float* __restrict__ out) {
    extern __shared__ float2 sm[];
    int row = blockIdx.x;
    int h   = row & (Hh - 1);
    int tid = threadIdx.x;
    const float2* u2 = (const float2*)(u + (size_t)row * Lq);

    float2 ur[8];
#pragma unroll
    for (int r = 0; r < 8; r++) ur[r] = u2[tid + (r << 8)];

    // forward FFT (packed real input, zero pad in upper half)
    fft_stage0_regs(sm, tid, ur);
    fft_stage1(sm, tid);
    fft_stage2_smem(sm, tid);

    // middle: split -> *G -> merge -> store conj (in-place read/sync/write)
    const float2* G = g_G + (size_t)h * GSTRIDE;
    float2 sa[8], sb[8], z2048;
#pragma unroll
    for (int r = 0; r < 8; r++) {
        int k = tid + (r << 8);
        sa[r] = sm[PD(k)];
        sb[r] = (k == 0) ? make_float2(0.f, 0.f) : sm[PD(4096 - k)];
    }
    if (tid == 0) z2048 = sm[PD(2048)];
    __syncthreads();
#pragma unroll
    for (int r = 0; r < 8; r++) {
        int k = tid + (r << 8);
        if (k == 0) {
            float2 z0 = sa[0];
            float x0 = z0.x + z0.y;
            float xM = z0.x - z0.y;
            float y0 = x0 * G[0].x;
            float yM = xM * G[4096].x;
            sm[PD(0)] = make_float2(0.5f * (y0 + yM), -0.5f * (y0 - yM));
            sm[PD(2048)] = cmulf(make_float2(z2048.x, -z2048.y), G[2048]);
        } else {
            float2 zk = sa[r];
            float2 zm = sb[r];
            float2 xe = make_float2(0.5f * (zk.x + zm.x), 0.5f * (zk.y - zm.y));
            float2 xo = make_float2(0.5f * (zk.y + zm.y), -0.5f * (zk.x - zm.x));
            float2 w  = g_tw[k];
            float2 wxo = cmulf(w, xo);
            float2 xf = make_float2(xe.x + wxo.x, xe.y + wxo.y);
            float2 xb = make_float2(xe.x - wxo.x, -(xe.y - wxo.y));
            float2 ya = cmulf(xf, G[k]);
            float2 yb = cmulf(xb, G[4096 - k]);
            float2 ye = make_float2(0.5f * (ya.x + yb.x), 0.5f * (ya.y - yb.y));
            float2 dd = make_float2(ya.x - yb.x, ya.y + yb.y);
            float2 wc = make_float2(w.x, -w.y);
            float2 yo = cmulf(wc, dd);
            yo.x *= 0.5f; yo.y *= 0.5f;
            sm[PD(k)]        = make_float2(ye.x - yo.y, -(ye.y + yo.x));
            sm[PD(4096 - k)] = make_float2(ye.x + yo.y, ye.y - yo.x);
        }
    }
    __syncthreads();

    // inverse FFT: stage0 (full, twiddled), stage1, stage2 (unit) -> direct gmem
    fft_stage0_smem(sm, tid);
    fft_stage1(sm, tid);
    {
        float2 x[16];
#pragma unroll
        for (int r = 0; r < 16; r++) x[r] = sm[PD(tid + (r << 8))];
        float2 A0[4], A1[4], A2[4], A3[4];
        ALAYER(x, A0, A1, A2, A3);
        float2 y[8];
        BLAYER_UNIT_HALF(A0, A1, A2, A3, y);

        float dh = D[h];
        float2* o2 = (float2*)(out + (size_t)row * Lq);
        const float inv = 1.0f / (float)Mh;
#pragma unroll
        for (int m = 0; m < 8; m++) {
            float2 uu = ur[m];
            o2[tid + (m << 8)] = make_float2(fmaf(dh, uu.x, y[m].x * inv),
                                             fmaf(dh, uu.y, -y[m].y * inv));
        }
    }
}

// ---------------- launcher ----------------
extern "C" void kernel_launch(void* const* d_in, const int* in_sizes, int n_in,
                              void* d_out, int out_size) {
    const float* u  = (const float*)d_in[0];
    const float* W  = (const float*)d_in[1];
    const float* D  = (const float*)d_in[2];
    const float* ls = (const float*)d_in[3];
    const float* Lr = (const float*)d_in[4];
    const float* Li = (const float*)d_in[5];
    float* out = (float*)d_out;

    int fft_smem = PDN * (int)sizeof(float2);         // 34816 B
    int k_smem   = 4 * Lq * (int)sizeof(float);       // 65536 B

    cudaFuncSetAttribute(k_kernel,    cudaFuncAttributeMaxDynamicSharedMemorySize, k_smem);
    cudaFuncSetAttribute(fftG_kernel, cudaFuncAttributeMaxDynamicSharedMemorySize, fft_smem);
    cudaFuncSetAttribute(conv_kernel, cudaFuncAttributeMaxDynamicSharedMemorySize, fft_smem);

    tw_kernel<<<(NFFT / 2 + 255) / 256, 256>>>();
    coeff_kernel<<<Hh, Nn>>>(W, ls, Lr, Li);
    k_kernel<<<Hh, 256, k_smem>>>();
    fftG_kernel<<<Hh, 256, fft_smem>>>();
    conv_kernel<<<Bb * Hh, 256, fft_smem>>>(u, D, out);
}

// round 6
// speedup vs baseline: 3.9567x; 1.0142x over previous
#include <cuda_runtime.h>
#include <math.h>

#define Lq   4096
#define NFFT 8192
#define Mh   4096
#define Hh   512
#define Bb   8
#define Nn   64
#define GSTRIDE 4104

typedef unsigned long long ull;

__device__ float  g_K[Hh * Lq];
__device__ float2 g_G[Hh * GSTRIDE];
__device__ float2 g_tw[NFFT / 2];        // W_8192^j, j<4096
__device__ float4 g_coef[Hh * Nn];

#define PD(i) ((i) + ((i) >> 4))
#define PDN 4352

// ---------------- scalar complex helpers (twiddle chains only) ----------------
__device__ __forceinline__ float2 cmulf(float2 a, float2 b) {
    return make_float2(fmaf(a.x, b.x, -a.y * b.y), fmaf(a.x, b.y, a.y * b.x));
}

// ---------------- f32x2 packed primitives ----------------
__device__ __forceinline__ ull pk2(float lo, float hi){
    ull r; asm("mov.b64 %0,{%1,%2};":"=l"(r):"f"(lo),"f"(hi)); return r;
}
__device__ __forceinline__ void upk2(ull v, float& lo, float& hi){
    asm("mov.b64 {%0,%1},%2;":"=f"(lo),"=f"(hi):"l"(v));
}
__device__ __forceinline__ ull f2add(ull a, ull b){
    ull r; asm("add.rn.f32x2 %0,%1,%2;":"=l"(r):"l"(a),"l"(b)); return r;
}
__device__ __forceinline__ ull f2mul(ull a, ull b){
    ull r; asm("mul.rn.f32x2 %0,%1,%2;":"=l"(r):"l"(a),"l"(b)); return r;
}
__device__ __forceinline__ ull f2fma(ull a, ull b, ull c){
    ull r; asm("fma.rn.f32x2 %0,%1,%2,%3;":"=l"(r):"l"(a),"l"(b),"l"(c)); return r;
}
__device__ __forceinline__ ull f2sub(ull a, ull b){          // a - b
    return f2fma(b, pk2(-1.f, -1.f), a);
}
__device__ __forceinline__ ull f2neg(ull a){
    return f2mul(a, pk2(-1.f, -1.f));
}

// two-row packed complex: r = (reA, reB), i = (imA, imB)
struct c2 { ull r, i; };

__device__ __forceinline__ c2 c2add(c2 a, c2 b){ c2 o; o.r=f2add(a.r,b.r); o.i=f2add(a.i,b.i); return o; }
__device__ __forceinline__ c2 c2sub(c2 a, c2 b){ c2 o; o.r=f2sub(a.r,b.r); o.i=f2sub(a.i,b.i); return o; }
// a * w (w = lane-uniform complex constant)
__device__ __forceinline__ c2 c2mulw(c2 a, float2 w){
    ull wr = pk2(w.x, w.x), wi = pk2(w.y, w.y), nwi = pk2(-w.y, -w.y);
    c2 o;
    o.r = f2fma(a.r, wr, f2mul(a.i, nwi));
    o.i = f2fma(a.r, wi, f2mul(a.i, wr));
    return o;
}
// a * (-i)  = (a.i, -a.r)
__device__ __forceinline__ c2 c2mulni(c2 a){ c2 o; o.r = a.i; o.i = f2neg(a.r); return o; }

// ---------------- packed DFT4s ----------------
#define DFT4P(p0,p1,p2,p3,q0,q1,q2,q3) { \
    c2 t0=c2add(p0,p2), t1=c2sub(p0,p2), t2=c2add(p1,p3), t3=c2sub(p1,p3); \
    q0=c2add(t0,t2); q2=c2sub(t0,t2); \
    q1.r=f2add(t1.r,t3.i); q1.i=f2sub(t1.i,t3.r); \
    q3.r=f2sub(t1.r,t3.i); q3.i=f2add(t1.i,t3.r); }

#define DFT4HP(p0,p1,q0,q1,q2,q3) { \
    q0=c2add(p0,p1); q2=c2sub(p0,p1); \
    q1.r=f2add(p0.r,p1.i); q1.i=f2sub(p0.i,p1.r); \
    q3.r=f2sub(p0.r,p1.i); q3.i=f2add(p0.i,p1.r); }

#define DFT4_01P(p0,p1,p2,p3,q0,q1) { \
    c2 t0=c2add(p0,p2), t1=c2sub(p0,p2), t2=c2add(p1,p3), t3=c2sub(p1,p3); \
    q0=c2add(t0,t2); \
    q1.r=f2add(t1.r,t3.i); q1.i=f2sub(t1.i,t3.r); }

#define W16_1 make_float2( 0.9238795325112867f, -0.3826834323650898f)
#define W16_2 make_float2( 0.7071067811865476f, -0.7071067811865476f)
#define W16_3 make_float2( 0.3826834323650898f, -0.9238795325112867f)
#define W16_6 make_float2(-0.7071067811865476f, -0.7071067811865476f)
#define W16_9 make_float2(-0.9238795325112867f,  0.3826834323650898f)

#define ALAYERP(x,A0,A1,A2,A3) { \
    DFT4P(x[0],x[4],x[8],x[12], A0[0],A0[1],A0[2],A0[3]); \
    DFT4P(x[1],x[5],x[9],x[13], A1[0],A1[1],A1[2],A1[3]); \
    DFT4P(x[2],x[6],x[10],x[14],A2[0],A2[1],A2[2],A2[3]); \
    DFT4P(x[3],x[7],x[11],x[15],A3[0],A3[1],A3[2],A3[3]); }

#define ALAYER_HALFP(z,A0,A1,A2,A3) { \
    DFT4HP(z[0],z[4],A0[0],A0[1],A0[2],A0[3]); \
    DFT4HP(z[1],z[5],A1[0],A1[1],A1[2],A1[3]); \
    DFT4HP(z[2],z[6],A2[0],A2[1],A2[2],A2[3]); \
    DFT4HP(z[3],z[7],A3[0],A3[1],A3[2],A3[3]); }

#define BLAYER_TWP(A0,A1,A2,A3,y,W1IN) { \
    float2 w1=(W1IN); \
    float2 w2=cmulf(w1,w1), w3=cmulf(w2,w1), w4=cmulf(w2,w2); \
    float2 w8=cmulf(w4,w4), w12=cmulf(w8,w4); \
    DFT4P(A0[0],A1[0],A2[0],A3[0], y[0],y[4],y[8],y[12]); \
    { c2 v0=c2mulw(A0[1],w1); \
      c2 v1=c2mulw(A1[1],cmulf(W16_1,w1)); \
      c2 v2=c2mulw(A2[1],cmulf(W16_2,w1)); \
      c2 v3=c2mulw(A3[1],cmulf(W16_3,w1)); \
      DFT4P(v0,v1,v2,v3, y[1],y[5],y[9],y[13]); } \
    { c2 v0=c2mulw(A0[2],w2); \
      c2 v1=c2mulw(A1[2],cmulf(W16_2,w2)); \
      c2 v2=c2mulw(A2[2],make_float2(w2.y,-w2.x)); \
      c2 v3=c2mulw(A3[2],cmulf(W16_6,w2)); \
      DFT4P(v0,v1,v2,v3, y[2],y[6],y[10],y[14]); } \
    { c2 v0=c2mulw(A0[3],w3); \
      c2 v1=c2mulw(A1[3],cmulf(W16_3,w3)); \
      c2 v2=c2mulw(A2[3],cmulf(W16_6,w3)); \
      c2 v3=c2mulw(A3[3],cmulf(W16_9,w3)); \
      DFT4P(v0,v1,v2,v3, y[3],y[7],y[11],y[15]); } \
    _Pragma("unroll") \
    for (int m1=0;m1<4;m1++){ \
        y[m1+4]=c2mulw(y[m1+4],w4); y[m1+8]=c2mulw(y[m1+8],w8); y[m1+12]=c2mulw(y[m1+12],w12); } }

#define BLAYER_UNITP(A0,A1,A2,A3,y) { \
    DFT4P(A0[0],A1[0],A2[0],A3[0], y[0],y[4],y[8],y[12]); \
    { c2 v1=c2mulw(A1[1],W16_1), v2=c2mulw(A2[1],W16_2), v3=c2mulw(A3[1],W16_3); \
      DFT4P(A0[1],v1,v2,v3, y[1],y[5],y[9],y[13]); } \
    { c2 v1=c2mulw(A1[2],W16_2); \
      c2 v2=c2mulni(A2[2]); \
      c2 v3=c2mulw(A3[2],W16_6); \
      DFT4P(A0[2],v1,v2,v3, y[2],y[6],y[10],y[14]); } \
    { c2 v1=c2mulw(A1[3],W16_3), v2=c2mulw(A2[3],W16_6), v3=c2mulw(A3[3],W16_9); \
      DFT4P(A0[3],v1,v2,v3, y[3],y[7],y[11],y[15]); } }

#define BLAYER_UNIT_HALFP(A0,A1,A2,A3,y) { \
    DFT4_01P(A0[0],A1[0],A2[0],A3[0], y[0],y[4]); \
    { c2 v1=c2mulw(A1[1],W16_1), v2=c2mulw(A2[1],W16_2), v3=c2mulw(A3[1],W16_3); \
      DFT4_01P(A0[1],v1,v2,v3, y[1],y[5]); } \
    { c2 v1=c2mulw(A1[2],W16_2); \
      c2 v2=c2mulni(A2[2]); \
      c2 v3=c2mulw(A3[2],W16_6); \
      DFT4_01P(A0[2],v1,v2,v3, y[2],y[6]); } \
    { c2 v1=c2mulw(A1[3],W16_3), v2=c2mulw(A2[3],W16_6), v3=c2mulw(A3[3],W16_9); \
      DFT4_01P(A0[3],v1,v2,v3, y[3],y[7]); } }

// ---------------- twiddle table ----------------
__global__ void tw_kernel() {
    int j = blockIdx.x * blockDim.x + threadIdx.x;
    if (j < NFFT / 2) {
        double a = -2.0 * M_PI * (double)j / (double)NFFT;
        double s, c;
        sincos(a, &s, &c);
        g_tw[j] = make_float2((float)c, (float)s);
    }
}

// ---------------- coeff kernel (verified) ----------------
__global__ void coeff_kernel(const float* __restrict__ W,
                             const float* __restrict__ log_step,
                             const float* __restrict__ Lre,
                             const float* __restrict__ Lim) {
    int h = blockIdx.x;
    int n = threadIdx.x;
    float step = expf(log_step[h]);
    float Lr = Lre[n], Li = Lim[n];
    float qr = step * Lr, qi = step * Li;

    double sgn = (qr > 0.f) ? -1.0 : 1.0;
    double pr = sgn * (double)qr, pi = sgn * (double)qi;

    double eL = exp(pr * (double)Lq);
    double sL, cL;
    sincos(pi * (double)Lq, &sL, &cL);
    double num_re = eL * cL - 1.0;
    double num_im = eL * sL;

    double sp, cp;
    sincos(pi, &sp, &cp);
    double em1 = expm1(pr);
    double hs  = sin(0.5 * pi);
    double den_re = em1 * cp - 2.0 * hs * hs;
    double den_im = (em1 + 1.0) * sp;
    double dmag = den_re * den_re + den_im * den_im;

    double s_re, s_im;
    if (dmag > 0.0) {
        s_re = (num_re * den_re + num_im * den_im) / dmag;
        s_im = (num_im * den_re - num_re * den_im) / dmag;
    } else {
        s_re = (double)Lq;
        s_im = 0.0;
    }

    double w0 = W[(h * Nn + n) * 2 + 0];
    double w1 = W[(h * Nn + n) * 2 + 1];
    double lmag = (double)Lr * Lr + (double)Li * Li;
    double a_re = (w0 * Lr + w1 * Li) / lmag;
    double a_im = (w1 * Lr - w0 * Li) / lmag;
    double smag = s_re * s_re + s_im * s_im + 1e-7;
    double b_re =  s_re / smag;
    double b_im = -s_im / smag;
    float cr = (float)(a_re * b_re - a_im * b_im);
    float ci = (float)(a_re * b_im + a_im * b_re);
    g_coef[h * Nn + n] = make_float4(qr, qi, cr, ci);
}

// ---------------- K via f32x2 packed recurrence (verified) ----------------
__global__ __launch_bounds__(256) void k_kernel() {
    extern __shared__ float kbuf[];
    int h   = blockIdx.x;
    int tid = threadIdx.x;
    int cp  = tid & 63;
    int g   = tid >> 6;
    int l0a = cp * 32;
    int l0b = l0a + 2048;

    ull acc[32];
#pragma unroll
    for (int j = 0; j < 32; j++) acc[j] = 0ULL;

    for (int nn = 0; nn < 16; nn++) {
        int n = (g << 4) + nn;
        float4 cf = g_coef[h * Nn + n];
        float qr = cf.x, qi = cf.y, cr = cf.z, ci = cf.w;
        bool fwd = (qr <= 0.f);

        float ara, aia, arb, aib, lrS, liS;
        if (fwd) {
            float d0a = (float)l0a, d0b = (float)l0b;
            float ma = expf(qr * d0a), mb = expf(qr * d0b);
            float sa, ca2, sb, cb2;
            sincosf(qi * d0a, &sa, &ca2);
            sincosf(qi * d0b, &sb, &cb2);
            ara = ma * ca2; aia = ma * sa;
            arb = mb * cb2; aib = mb * sb;
            float em = expf(qr);
            float sl, cl2; sincosf(qi, &sl, &cl2);
            lrS = em * cl2; liS = em * sl;
        } else {
            float d0a = (float)(l0a + 31 - (Lq - 1));
            float d0b = (float)(l0b + 31 - (Lq - 1));
            float ma = expf(qr * d0a), mb = expf(qr * d0b);
            float sa, ca2, sb, cb2;
            sincosf(qi * d0a, &sa, &ca2);
            sincosf(qi * d0b, &sb, &cb2);
            ara = ma * ca2; aia = ma * sa;
            arb = mb * cb2; aib = mb * sb;
            float em = expf(-qr);
            float sl, cl2; sincosf(-qi, &sl, &cl2);
            lrS = em * cl2; liS = em * sl;
        }

        ull ar2 = pk2(ara, arb), ai2 = pk2(aia, aib);
        ull lr2 = pk2(lrS, lrS), li2 = pk2(liS, liS);
        ull nli2 = pk2(-liS, -liS);
        ull cr2 = pk2(cr, cr),  nci2 = pk2(-ci, -ci);

        if (fwd) {
#pragma unroll
            for (int j = 0; j < 32; j++) {
                acc[j] = f2fma(cr2, ar2, f2fma(nci2, ai2, acc[j]));
                ull t = f2fma(ar2, lr2, f2mul(ai2, nli2));
                ai2 = f2fma(ar2, li2, f2mul(ai2, lr2));
                ar2 = t;
            }
        } else {
#pragma unroll
            for (int j = 31; j >= 0; j--) {
                acc[j] = f2fma(cr2, ar2, f2fma(nci2, ai2, acc[j]));
                ull t = f2fma(ar2, lr2, f2mul(ai2, nli2));
                ai2 = f2fma(ar2, li2, f2mul(ai2, lr2));
                ar2 = t;
            }
        }
    }

#pragma unroll
    for (int j = 0; j < 32; j++) {
        float a, b; upk2(acc[j], a, b);
        kbuf[g * Lq + l0a + j] = a;
        kbuf[g * Lq + l0b + j] = b;
    }
    __syncthreads();
    for (int i = tid; i < Lq; i += 256) {
        g_K[h * Lq + i] = kbuf[i] + kbuf[Lq + i] + kbuf[2 * Lq + i] + kbuf[3 * Lq + i];
    }
}

// ---------------- packed FFT stages (Xr/Xi = packed re/im planes) ----------------
__device__ __forceinline__ void fft_stage0_regsP(ull* Xr, ull* Xi, int tid, const c2 z[8]) {
    c2 A0[4], A1[4], A2[4], A3[4];
    ALAYER_HALFP(z, A0, A1, A2, A3);
    c2 y[16];
    BLAYER_TWP(A0, A1, A2, A3, y, g_tw[tid << 1]);
    int ob = tid << 4;
#pragma unroll
    for (int m = 0; m < 16; m++) { int idx = PD(ob + m); Xr[idx] = y[m].r; Xi[idx] = y[m].i; }
    __syncthreads();
}

__device__ __forceinline__ void fft_stage0_smemP(ull* Xr, ull* Xi, int tid) {
    c2 x[16];
#pragma unroll
    for (int r = 0; r < 16; r++) { int idx = PD(tid + (r << 8)); x[r].r = Xr[idx]; x[r].i = Xi[idx]; }
    __syncthreads();
    c2 A0[4], A1[4], A2[4], A3[4];
    ALAYERP(x, A0, A1, A2, A3);
    c2 y[16];
    BLAYER_TWP(A0, A1, A2, A3, y, g_tw[tid << 1]);
    int ob = tid << 4;
#pragma unroll
    for (int m = 0; m < 16; m++) { int idx = PD(ob + m); Xr[idx] = y[m].r; Xi[idx] = y[m].i; }
    __syncthreads();
}

__device__ __forceinline__ void fft_stage1P(ull* Xr, ull* Xi, int tid) {
    int q = tid & 15, pp = tid - q;
    c2 x[16];
#pragma unroll
    for (int r = 0; r < 16; r++) { int idx = PD(tid + (r << 8)); x[r].r = Xr[idx]; x[r].i = Xi[idx]; }
    __syncthreads();
    c2 A0[4], A1[4], A2[4], A3[4];
    ALAYERP(x, A0, A1, A2, A3);
    c2 y[16];
    BLAYER_TWP(A0, A1, A2, A3, y, g_tw[pp << 1]);
    int ob = (pp << 4) + q;
#pragma unroll
    for (int m = 0; m < 16; m++) { int idx = PD(ob + (m << 4)); Xr[idx] = y[m].r; Xi[idx] = y[m].i; }
    __syncthreads();
}

__device__ __forceinline__ void fft_stage2P(ull* Xr, ull* Xi, int tid) {
    c2 x[16];
#pragma unroll
    for (int r = 0; r < 16; r++) { int idx = PD(tid + (r << 8)); x[r].r = Xr[idx]; x[r].i = Xi[idx]; }
    __syncthreads();
    c2 A0[4], A1[4], A2[4], A3[4];
    ALAYERP(x, A0, A1, A2, A3);
    c2 y[16];
    BLAYER_UNITP(A0, A1, A2, A3, y);
#pragma unroll
    for (int m = 0; m < 16; m++) { int idx = PD(tid + (m << 8)); Xr[idx] = y[m].r; Xi[idx] = y[m].i; }
    __syncthreads();
}

// ---------------- rfft8192(K) -> G, two h-rows per block ----------------
__global__ __launch_bounds__(256, 2) void fftG_kernel() {
    extern __shared__ ull smu[];
    ull* Xr = smu;
    ull* Xi = smu + PDN;
    int h0 = blockIdx.x, h1 = h0 + 256;
    int tid = threadIdx.x;
    const float2* kA = (const float2*)(g_K + (size_t)h0 * Lq);
    const float2* kB = (const float2*)(g_K + (size_t)h1 * Lq);
    c2 z[8];
#pragma unroll
    for (int r = 0; r < 8; r++) {
        float2 a = kA[tid + (r << 8)], b = kB[tid + (r << 8)];
        z[r].r = pk2(a.x, b.x);
        z[r].i = pk2(a.y, b.y);
    }

    fft_stage0_regsP(Xr, Xi, tid, z);
    fft_stage1P(Xr, Xi, tid);
    fft_stage2P(Xr, Xi, tid);

    float2* G0 = g_G + (size_t)h0 * GSTRIDE;
    float2* G1 = g_G + (size_t)h1 * GSTRIDE;
#pragma unroll
    for (int r = 0; r < 8; r++) {
        int k = tid + (r << 8);
        if (k == 0) {
            c2 z0; z0.r = Xr[PD(0)]; z0.i = Xi[PD(0)];
            ull s = f2add(z0.r, z0.i);
            ull d = f2sub(z0.r, z0.i);
            float sa, sb, da, db; upk2(s, sa, sb); upk2(d, da, db);
            G0[0] = make_float2(sa, 0.f);    G1[0] = make_float2(sb, 0.f);
            G0[4096] = make_float2(da, 0.f); G1[4096] = make_float2(db, 0.f);
            c2 z2; z2.r = Xr[PD(2048)]; z2.i = f2neg(Xi[PD(2048)]);
            float ra, rb, ia, ib; upk2(z2.r, ra, rb); upk2(z2.i, ia, ib);
            G0[2048] = make_float2(ra, ia);  G1[2048] = make_float2(rb, ib);
        } else {
            c2 zk, zm;
            zk.r = Xr[PD(k)];        zk.i = Xi[PD(k)];
            zm.r = Xr[PD(4096 - k)]; zm.i = Xi[PD(4096 - k)];
            ull half = pk2(0.5f, 0.5f), nhalf = pk2(-0.5f, -0.5f);
            c2 xe, xo;
            xe.r = f2mul(f2add(zk.r, zm.r), half);
            xe.i = f2mul(f2sub(zk.i, zm.i), half);
            xo.r = f2mul(f2add(zk.i, zm.i), half);
            xo.i = f2mul(f2sub(zk.r, zm.r), nhalf);
            float2 w = g_tw[k];
            c2 wxo = c2mulw(xo, w);
            c2 gf, gb;
            gf.r = f2add(xe.r, wxo.r); gf.i = f2add(xe.i, wxo.i);
            gb.r = f2sub(xe.r, wxo.r); gb.i = f2neg(f2sub(xe.i, wxo.i));
            float ra, rb, ia, ib;
            upk2(gf.r, ra, rb); upk2(gf.i, ia, ib);
            G0[k] = make_float2(ra, ia); G1[k] = make_float2(rb, ib);
            upk2(gb.r, ra, rb); upk2(gb.i, ia, ib);
            G0[4096 - k] = make_float2(ra, ia); G1[4096 - k] = make_float2(rb, ib);
        }
    }
}

// ---------------- conv: two (b,h) rows per block, fully f32x2 packed --------------
__global__ __launch_bounds__(256, 2) void conv_kernel(const float* __restrict__ u,
                                                      const float* __restrict__ D,
                                                      float* __restrict__ out) {
    extern __shared__ ull smu[];
    ull* Xr = smu;
    ull* Xi = smu + PDN;
    int blk = blockIdx.x;                 // 0..2047
    int h   = blk & (Hh - 1);
    int bp  = blk >> 9;                   // 0..3
    size_t rowA = (size_t)(2 * bp) * Hh + h;
    size_t rowB = rowA + Hh;
    int tid = threadIdx.x;
    const float2* uA = (const float2*)(u + rowA * Lq);
    const float2* uB = (const float2*)(u + rowB * Lq);

    c2 ur[8];
#pragma unroll
    for (int r = 0; r < 8; r++) {
        float2 a = uA[tid + (r << 8)], b = uB[tid + (r << 8)];
        ur[r].r = pk2(a.x, b.x);
        ur[r].i = pk2(a.y, b.y);
    }

    // forward FFT (packed real input, upper half zero)
    fft_stage0_regsP(Xr, Xi, tid, ur);
    fft_stage1P(Xr, Xi, tid);
    fft_stage2P(Xr, Xi, tid);

    // middle: split -> *G -> merge -> store conj
    const float2* G = g_G + (size_t)h * GSTRIDE;
    c2 sa[8], sb[8], z2048;
#pragma unroll
    for (int r = 0; r < 8; r++) {
        int k = tid + (r << 8);
        sa[r].r = Xr[PD(k)]; sa[r].i = Xi[PD(k)];
        if (k == 0) { sb[r].r = 0ULL; sb[r].i = 0ULL; }
        else        { sb[r].r = Xr[PD(4096 - k)]; sb[r].i = Xi[PD(4096 - k)]; }
    }
    if (tid == 0) { z2048.r = Xr[PD(2048)]; z2048.i = Xi[PD(2048)]; }
    __syncthreads();
#pragma unroll
    for (int r = 0; r < 8; r++) {
        int k = tid + (r << 8);
        ull half = pk2(0.5f, 0.5f), nhalf = pk2(-0.5f, -0.5f);
        if (k == 0) {
            c2 z0 = sa[0];
            ull x0 = f2add(z0.r, z0.i);
            ull xM = f2sub(z0.r, z0.i);
            ull y0 = f2mul(x0, pk2(G[0].x, G[0].x));
            ull yM = f2mul(xM, pk2(G[4096].x, G[4096].x));
            Xr[PD(0)] = f2mul(f2add(y0, yM), half);
            Xi[PD(0)] = f2mul(f2sub(y0, yM), nhalf);
            c2 t; t.r = z2048.r; t.i = f2neg(z2048.i);
            c2 p = c2mulw(t, G[2048]);
            Xr[PD(2048)] = p.r; Xi[PD(2048)] = p.i;
        } else {
            c2 zk = sa[r], zm = sb[r];
            c2 xe, xo;
            xe.r = f2mul(f2add(zk.r, zm.r), half);
            xe.i = f2mul(f2sub(zk.i, zm.i), half);
            xo.r = f2mul(f2add(zk.i, zm.i), half);
            xo.i = f2mul(f2sub(zk.r, zm.r), nhalf);
            float2 w = g_tw[k];
            c2 wxo = c2mulw(xo, w);
            c2 xf, xb;
            xf.r = f2add(xe.r, wxo.r); xf.i = f2add(xe.i, wxo.i);
            xb.r = f2sub(xe.r, wxo.r); xb.i = f2neg(f2sub(xe.i, wxo.i));
            c2 ya = c2mulw(xf, G[k]);
            c2 yb = c2mulw(xb, G[4096 - k]);
            c2 ye, dd;
            ye.r = f2mul(f2add(ya.r, yb.r), half);
            ye.i = f2mul(f2sub(ya.i, yb.i), half);
            dd.r = f2sub(ya.r, yb.r);
            dd.i = f2add(ya.i, yb.i);
            c2 yo = c2mulw(dd, make_float2(w.x, -w.y));
            yo.r = f2mul(yo.r, half); yo.i = f2mul(yo.i, half);
            // store conj(Zy)
            Xr[PD(k)] = f2sub(ye.r, yo.i);
            Xi[PD(k)] = f2neg(f2add(ye.i, yo.r));
            Xr[PD(4096 - k)] = f2add(ye.r, yo.i);
            Xi[PD(4096 - k)] = f2sub(ye.i, yo.r);
        }
    }
    __syncthreads();

    // inverse FFT
    fft_stage0_smemP(Xr, Xi, tid);
    fft_stage1P(Xr, Xi, tid);
    {
        c2 x[16];
#pragma unroll
        for (int r = 0; r < 16; r++) { int idx = PD(tid + (r << 8)); x[r].r = Xr[idx]; x[r].i = Xi[idx]; }
        c2 A0[4], A1[4], A2[4], A3[4];
        ALAYERP(x, A0, A1, A2, A3);
        c2 y[8];
        BLAYER_UNIT_HALFP(A0, A1, A2, A3, y);

        float dh = D[h];
        ull dh2 = pk2(dh, dh);
        ull inv2 = pk2(1.0f / Mh, 1.0f / Mh);
        ull ninv2 = pk2(-1.0f / Mh, -1.0f / Mh);
        float2* oA = (float2*)(out + rowA * Lq);
        float2* oB = (float2*)(out + rowB * Lq);
#pragma unroll
        for (int m = 0; m < 8; m++) {
            ull resr = f2fma(ur[m].r, dh2, f2mul(y[m].r, inv2));
            ull resi = f2fma(ur[m].i, dh2, f2mul(y[m].i, ninv2));
            float ra, rb, ia, ib;
            upk2(resr, ra, rb); upk2(resi, ia, ib);
            oA[tid + (m << 8)] = make_float2(ra, ia);
            oB[tid + (m << 8)] = make_float2(rb, ib);
        }
    }
}

// ---------------- launcher ----------------
extern "C" void kernel_launch(void* const* d_in, const int* in_sizes, int n_in,
                              void* d_out, int out_size) {
    const float* u  = (const float*)d_in[0];
    const float* W  = (const float*)d_in[1];
    const float* D  = (const float*)d_in[2];
    const float* ls = (const float*)d_in[3];
    const float* Lr = (const float*)d_in[4];
    const float* Li = (const float*)d_in[5];
    float* out = (float*)d_out;

    int fft_smem = 2 * PDN * (int)sizeof(ull);        // 69632 B
    int k_smem   = 4 * Lq * (int)sizeof(float);       // 65536 B

    cudaFuncSetAttribute(k_kernel,    cudaFuncAttributeMaxDynamicSharedMemorySize, k_smem);
    cudaFuncSetAttribute(fftG_kernel, cudaFuncAttributeMaxDynamicSharedMemorySize, fft_smem);
    cudaFuncSetAttribute(conv_kernel, cudaFuncAttributeMaxDynamicSharedMemorySize, fft_smem);

    tw_kernel<<<(NFFT / 2 + 255) / 256, 256>>>();
    coeff_kernel<<<Hh, Nn>>>(W, ls, Lr, Li);
    k_kernel<<<Hh, 256, k_smem>>>();
    fftG_kernel<<<Hh / 2, 256, fft_smem>>>();
    conv_kernel<<<Bb * Hh / 2, 256, fft_smem>>>(u, D, out);
}